// round 4
// baseline (speedup 1.0000x reference)
#include <cuda_runtime.h>
#include <math.h>
#include <stdint.h>

#define NS 100
#define ND 20
#define NT 30
#define NH_ 64
#define NHEADS 8
#define FTXT 512
#define FPRC 3
#define G3 192   // 3*H

// ---------------- scratch (device globals; no allocs allowed) ----------------
__device__ float g_gi_text[(size_t)NS * ND * NT * G3];   // [s][d*30+t][192]  ~46MB
__device__ float g_news[NS * ND * NH_];                  // [s][d][64]
__device__ float g_price_vec[NS * NH_];
__device__ float g_text_vec[NS * NH_];
__device__ float g_feature[NS * NH_];
__device__ float g_out1[NS * 2];
__device__ float g_xcat[NS * NHEADS * NH_];              // [i][head*64+k]

__device__ __forceinline__ float sigf(float x) { return 1.f / (1.f + expf(-x)); }
__device__ __forceinline__ float eluf(float x) { return x > 0.f ? x : expm1f(x); }

// ---------------- Kernel A: per-stock GEMM  gi = X @ Wih^T + bih -------------
// X: [600,512] (text_input[s]), W: [192,512], C: [600,192]
__global__ __launch_bounds__(256) void text_gemm(
    const float* __restrict__ X, const float* __restrict__ W,
    const float* __restrict__ bih) {
  const int s  = blockIdx.z;
  const int m0 = blockIdx.x * 64;
  const int n0 = blockIdx.y * 64;
  const float* Xs = X + (size_t)s * 600 * 512;
  const float* Ws = W + (size_t)s * 192 * 512;

  __shared__ float As[16][68];
  __shared__ float Bs[16][68];

  const int tx = threadIdx.x, ty = threadIdx.y;
  const int tid = ty * 16 + tx;
  const int lm  = tid >> 2;          // 0..63
  const int lk4 = (tid & 3) * 4;     // 0,4,8,12

  float c[4][4] = {};

  for (int k0 = 0; k0 < 512; k0 += 16) {
    float4 av = make_float4(0.f, 0.f, 0.f, 0.f);
    int gm = m0 + lm;
    if (gm < 600) av = *(const float4*)(Xs + (size_t)gm * 512 + k0 + lk4);
    As[lk4 + 0][lm] = av.x; As[lk4 + 1][lm] = av.y;
    As[lk4 + 2][lm] = av.z; As[lk4 + 3][lm] = av.w;
    float4 bv = *(const float4*)(Ws + (size_t)(n0 + lm) * 512 + k0 + lk4);
    Bs[lk4 + 0][lm] = bv.x; Bs[lk4 + 1][lm] = bv.y;
    Bs[lk4 + 2][lm] = bv.z; Bs[lk4 + 3][lm] = bv.w;
    __syncthreads();
#pragma unroll
    for (int kk = 0; kk < 16; kk++) {
      float a[4], b[4];
      *(float4*)a = *(const float4*)&As[kk][ty * 4];
      *(float4*)b = *(const float4*)&Bs[kk][tx * 4];
#pragma unroll
      for (int i = 0; i < 4; i++)
#pragma unroll
        for (int j = 0; j < 4; j++) c[i][j] += a[i] * b[j];
    }
    __syncthreads();
  }
#pragma unroll
  for (int i = 0; i < 4; i++) {
    int gm = m0 + ty * 4 + i;
    if (gm >= 600) continue;
#pragma unroll
    for (int j = 0; j < 4; j++) {
      int gn = n0 + tx * 4 + j;
      g_gi_text[((size_t)s * 600 + gm) * 192 + gn] = c[i][j] + bih[s * 192 + gn];
    }
  }
}

// ---------------- Kernel B: text GRU recurrence + attention pool -------------
// one block per (s,d); 192 threads. smem: WhhT[64*192] outs[30*64] h[64] gh[192] sc[32] at[32]
#define TEXT_RNN_SMEM ((64 * 192 + 30 * 64 + 64 + 192 + 32 + 32) * 4)
__global__ __launch_bounds__(192) void text_rnn(
    const float* __restrict__ Whh, const float* __restrict__ bhh,
    const float* __restrict__ Wa) {
  const int sd = blockIdx.x;
  const int s = sd / ND, d = sd % ND;
  extern __shared__ float sm[];
  float* WhhT  = sm;                 // [k][g] : k*192+g
  float* outs  = WhhT + 64 * 192;    // [30][64]
  float* hbuf  = outs + 30 * 64;
  float* gh    = hbuf + 64;
  float* sc    = gh + 192;
  float* at    = sc + 32;
  const int tid = threadIdx.x;

  const float* Whs = Whh + (size_t)s * 192 * 64;
  for (int idx = tid; idx < 192 * 64; idx += 192) {
    int g = idx >> 6, k = idx & 63;
    WhhT[k * 192 + g] = Whs[idx];
  }
  if (tid < 64) hbuf[tid] = 0.f;
  const float bh = bhh[s * 192 + tid];
  const float* gib = g_gi_text + ((size_t)s * 600 + d * 30) * 192;
  __syncthreads();

  for (int t = 0; t < 30; t++) {
    float acc = bh;
#pragma unroll
    for (int k = 0; k < 64; k++) acc += WhhT[k * 192 + tid] * hbuf[k];
    gh[tid] = acc;
    __syncthreads();
    if (tid < 64) {
      const float* gi = gib + t * 192;
      float r = sigf(gi[tid] + gh[tid]);
      float z = sigf(gi[64 + tid] + gh[64 + tid]);
      float n = tanhf(gi[128 + tid] + r * gh[128 + tid]);
      float hn = (1.f - z) * n + z * hbuf[tid];
      hbuf[tid] = hn;
      outs[t * 64 + tid] = hn;
    }
    __syncthreads();
  }

  // attention pool: s_t = tanh(outs_t @ Wa) . h_last ; softmax over t ; a @ outs
  const float* Was = Wa + (size_t)s * 64 * 64;
  const int w = tid >> 5, lane = tid & 31;
  for (int tt = 0; tt < 5; tt++) {
    int t = w * 5 + tt;
    float sacc = 0.f;
#pragma unroll
    for (int kh = 0; kh < 2; kh++) {
      int k = lane + kh * 32;
      float p = 0.f;
#pragma unroll
      for (int j = 0; j < 64; j++) p += outs[t * 64 + j] * Was[j * 64 + k];
      sacc += tanhf(p) * hbuf[k];
    }
    for (int o = 16; o; o >>= 1) sacc += __shfl_xor_sync(0xffffffffu, sacc, o);
    if (lane == 0) sc[t] = sacc;
  }
  __syncthreads();
  if (tid < 32) {
    float v = (tid < 30) ? sc[tid] : -INFINITY;
    float m = v;
    for (int o = 16; o; o >>= 1) m = fmaxf(m, __shfl_xor_sync(0xffffffffu, m, o));
    float e = (tid < 30) ? expf(v - m) : 0.f;
    float su = e;
    for (int o = 16; o; o >>= 1) su += __shfl_xor_sync(0xffffffffu, su, o);
    if (tid < 30) at[tid] = e / su;
  }
  __syncthreads();
  if (tid < 64) {
    float acc = 0.f;
    for (int t = 0; t < 30; t++) acc += at[t] * outs[t * 64 + tid];
    g_news[(s * ND + d) * 64 + tid] = acc;
  }
}

// ---------------- Kernel C: price GRU + attention ----------------------------
#define PRICE_SMEM ((64 * 192 + 20 * 64 + 64 + 192 + 192 + 32 + 32) * 4)
__global__ __launch_bounds__(192) void price_rnn(
    const float* __restrict__ price, const float* __restrict__ Wih,
    const float* __restrict__ Whh, const float* __restrict__ bih,
    const float* __restrict__ bhh, const float* __restrict__ Wa) {
  const int s = blockIdx.x;
  extern __shared__ float sm[];
  float* WhhT = sm;
  float* outs = WhhT + 64 * 192;   // [20][64]
  float* hbuf = outs + 20 * 64;
  float* gh   = hbuf + 64;
  float* gis  = gh + 192;
  float* sc   = gis + 192;
  float* at   = sc + 32;
  const int tid = threadIdx.x;

  const float* Whs = Whh + (size_t)s * 192 * 64;
  for (int idx = tid; idx < 192 * 64; idx += 192) {
    int g = idx >> 6, k = idx & 63;
    WhhT[k * 192 + g] = Whs[idx];
  }
  if (tid < 64) hbuf[tid] = 0.f;
  const float bh = bhh[s * 192 + tid];
  const float bi = bih[s * 192 + tid];
  const float wi0 = Wih[(s * 192 + tid) * 3 + 0];
  const float wi1 = Wih[(s * 192 + tid) * 3 + 1];
  const float wi2 = Wih[(s * 192 + tid) * 3 + 2];
  __syncthreads();

  for (int t = 0; t < 20; t++) {
    const float* x = price + ((size_t)s * 20 + t) * 3;
    gis[tid] = bi + wi0 * x[0] + wi1 * x[1] + wi2 * x[2];
    float acc = bh;
#pragma unroll
    for (int k = 0; k < 64; k++) acc += WhhT[k * 192 + tid] * hbuf[k];
    gh[tid] = acc;
    __syncthreads();
    if (tid < 64) {
      float r = sigf(gis[tid] + gh[tid]);
      float z = sigf(gis[64 + tid] + gh[64 + tid]);
      float n = tanhf(gis[128 + tid] + r * gh[128 + tid]);
      float hn = (1.f - z) * n + z * hbuf[tid];
      hbuf[tid] = hn;
      outs[t * 64 + tid] = hn;
    }
    __syncthreads();
  }

  const float* Was = Wa + (size_t)s * 64 * 64;
  const int w = tid >> 5, lane = tid & 31;
  for (int t = w; t < 20; t += 6) {
    float sacc = 0.f;
#pragma unroll
    for (int kh = 0; kh < 2; kh++) {
      int k = lane + kh * 32;
      float p = 0.f;
#pragma unroll
      for (int j = 0; j < 64; j++) p += outs[t * 64 + j] * Was[j * 64 + k];
      sacc += tanhf(p) * hbuf[k];
    }
    for (int o = 16; o; o >>= 1) sacc += __shfl_xor_sync(0xffffffffu, sacc, o);
    if (lane == 0) sc[t] = sacc;
  }
  __syncthreads();
  if (tid < 32) {
    float v = (tid < 20) ? sc[tid] : -INFINITY;
    float m = v;
    for (int o = 16; o; o >>= 1) m = fmaxf(m, __shfl_xor_sync(0xffffffffu, m, o));
    float e = (tid < 20) ? expf(v - m) : 0.f;
    float su = e;
    for (int o = 16; o; o >>= 1) su += __shfl_xor_sync(0xffffffffu, su, o);
    if (tid < 20) at[tid] = e / su;
  }
  __syncthreads();
  if (tid < 64) {
    float acc = 0.f;
    for (int t = 0; t < 20; t++) acc += at[t] * outs[t * 64 + tid];
    g_price_vec[s * 64 + tid] = acc;
  }
}

// ---------------- Kernel D: day-sequence GRU + attention ---------------------
#define SEQ_SMEM ((64 * 192 * 2 + 20 * 64 * 2 + 64 + 192 + 192 + 32 + 32) * 4)
__global__ __launch_bounds__(192) void seq_rnn(
    const float* __restrict__ Wih, const float* __restrict__ Whh,
    const float* __restrict__ bih, const float* __restrict__ bhh,
    const float* __restrict__ Wa) {
  const int s = blockIdx.x;
  extern __shared__ float sm[];
  float* WihT = sm;                   // [k][g]
  float* WhhT = WihT + 64 * 192;
  float* ns   = WhhT + 64 * 192;      // [20][64]
  float* outs = ns + 20 * 64;
  float* hbuf = outs + 20 * 64;
  float* gh   = hbuf + 64;
  float* gis  = gh + 192;
  float* sc   = gis + 192;
  float* at   = sc + 32;
  const int tid = threadIdx.x;

  const float* Wis = Wih + (size_t)s * 192 * 64;
  const float* Whs = Whh + (size_t)s * 192 * 64;
  for (int idx = tid; idx < 192 * 64; idx += 192) {
    int g = idx >> 6, k = idx & 63;
    WihT[k * 192 + g] = Wis[idx];
    WhhT[k * 192 + g] = Whs[idx];
  }
  for (int idx = tid; idx < 20 * 64; idx += 192) ns[idx] = g_news[s * 20 * 64 + idx];
  if (tid < 64) hbuf[tid] = 0.f;
  const float bh = bhh[s * 192 + tid];
  const float bi = bih[s * 192 + tid];
  __syncthreads();

  for (int t = 0; t < 20; t++) {
    float gacc = bi;
    float acc = bh;
#pragma unroll
    for (int k = 0; k < 64; k++) {
      gacc += WihT[k * 192 + tid] * ns[t * 64 + k];
      acc  += WhhT[k * 192 + tid] * hbuf[k];
    }
    gis[tid] = gacc;
    gh[tid] = acc;
    __syncthreads();
    if (tid < 64) {
      float r = sigf(gis[tid] + gh[tid]);
      float z = sigf(gis[64 + tid] + gh[64 + tid]);
      float n = tanhf(gis[128 + tid] + r * gh[128 + tid]);
      float hn = (1.f - z) * n + z * hbuf[tid];
      hbuf[tid] = hn;
      outs[t * 64 + tid] = hn;
    }
    __syncthreads();
  }

  const float* Was = Wa + (size_t)s * 64 * 64;
  const int w = tid >> 5, lane = tid & 31;
  for (int t = w; t < 20; t += 6) {
    float sacc = 0.f;
#pragma unroll
    for (int kh = 0; kh < 2; kh++) {
      int k = lane + kh * 32;
      float p = 0.f;
#pragma unroll
      for (int j = 0; j < 64; j++) p += outs[t * 64 + j] * Was[j * 64 + k];
      sacc += tanhf(p) * hbuf[k];
    }
    for (int o = 16; o; o >>= 1) sacc += __shfl_xor_sync(0xffffffffu, sacc, o);
    if (lane == 0) sc[t] = sacc;
  }
  __syncthreads();
  if (tid < 32) {
    float v = (tid < 20) ? sc[tid] : -INFINITY;
    float m = v;
    for (int o = 16; o; o >>= 1) m = fmaxf(m, __shfl_xor_sync(0xffffffffu, m, o));
    float e = (tid < 20) ? expf(v - m) : 0.f;
    float su = e;
    for (int o = 16; o; o >>= 1) su += __shfl_xor_sync(0xffffffffu, su, o);
    if (tid < 20) at[tid] = e / su;
  }
  __syncthreads();
  if (tid < 64) {
    float acc = 0.f;
    for (int t = 0; t < 20; t++) acc += at[t] * outs[t * 64 + tid];
    g_text_vec[s * 64 + tid] = acc;
  }
}

// ---------------- Kernel E: bilinear fusion + blend linear -------------------
__global__ __launch_bounds__(256) void bilinear_k(
    const float* __restrict__ B, const float* __restrict__ bb,
    const float* __restrict__ blW, const float* __restrict__ blb) {
  const int s = blockIdx.x;
  __shared__ float tv[64], pv[64], feat[64];
  const int tid = threadIdx.x;
  if (tid < 64) { tv[tid] = g_text_vec[s * 64 + tid]; pv[tid] = g_price_vec[s * 64 + tid]; }
  __syncthreads();
  const int w = tid >> 5, lane = tid & 31;
  for (int o = w; o < 64; o += 8) {
    const float* Bo = B + ((size_t)s * 64 + o) * 4096;
    float acc = 0.f;
    for (int idx = lane; idx < 4096; idx += 32)
      acc += tv[idx >> 6] * Bo[idx] * pv[idx & 63];
    for (int of = 16; of; of >>= 1) acc += __shfl_xor_sync(0xffffffffu, acc, of);
    if (lane == 0) feat[o] = tanhf(acc + bb[s * 64 + o]);
  }
  __syncthreads();
  if (tid < 64) g_feature[s * 64 + tid] = feat[tid];
  if (tid < 2) {
    float a = blb[tid];
    for (int k = 0; k < 64; k++) a += feat[k] * blW[k * 2 + tid];
    g_out1[s * 2 + tid] = tanhf(a);
  }
}

// ---------------- Kernel F: 8 GAT heads --------------------------------------
#define GAT_SMEM ((6400 + 6400 + 4096 + 128 + 128 + 128 + 800) * 4)
__global__ __launch_bounds__(256) void gat_heads_k(
    const float* __restrict__ gatW, const float* __restrict__ gata,
    const float* __restrict__ adj) {
  const int hd = blockIdx.x;
  extern __shared__ float sm[];
  float* Fs = sm;            // [100][64]
  float* Hs = Fs + 6400;     // [100][64]
  float* Ws = Hs + 6400;     // [64][64]
  float* av = Ws + 4096;     // [128]
  float* f1 = av + 128;      // [100]
  float* f2 = f1 + 128;      // [100]
  float* att = f2 + 128;     // [8][100]
  const int tid = threadIdx.x;

  for (int idx = tid; idx < 6400; idx += 256) Fs[idx] = g_feature[idx];
  for (int idx = tid; idx < 4096; idx += 256) Ws[idx] = gatW[hd * 4096 + idx];
  if (tid < 128) av[tid] = gata[hd * 128 + tid];
  __syncthreads();
  for (int idx = tid; idx < 6400; idx += 256) {
    int i = idx >> 6, k = idx & 63;
    float acc = 0.f;
#pragma unroll
    for (int j = 0; j < 64; j++) acc += Fs[i * 64 + j] * Ws[j * 64 + k];
    Hs[idx] = acc;
  }
  __syncthreads();
  if (tid < 100) {
    float a1 = 0.f, a2 = 0.f;
    for (int k = 0; k < 64; k++) {
      float h = Hs[tid * 64 + k];
      a1 += h * av[k]; a2 += h * av[64 + k];
    }
    f1[tid] = a1; f2[tid] = a2;
  }
  __syncthreads();
  const int w = tid >> 5, lane = tid & 31;
  for (int i = w; i < 100; i += 8) {
    float fi = f1[i];
    float ev[4];
    float m = -INFINITY;
#pragma unroll
    for (int q = 0; q < 4; q++) {
      int j = lane + q * 32;
      float e = -INFINITY;
      if (j < 100 && adj[i * 100 + j] > 0.f) {
        e = fi + f2[j];
        e = e > 0.f ? e : 0.2f * e;
      }
      ev[q] = e;
      m = fmaxf(m, e);
    }
    for (int o = 16; o; o >>= 1) m = fmaxf(m, __shfl_xor_sync(0xffffffffu, m, o));
    float su = 0.f;
#pragma unroll
    for (int q = 0; q < 4; q++) {
      int j = lane + q * 32;
      float wv = (ev[q] == -INFINITY) ? 0.f : expf(ev[q] - m);
      if (j < 100) att[w * 100 + j] = wv;
      su += wv;
    }
    for (int o = 16; o; o >>= 1) su += __shfl_xor_sync(0xffffffffu, su, o);
    float inv = 1.f / su;
    __syncwarp();
#pragma unroll
    for (int kh = 0; kh < 2; kh++) {
      int k = lane + kh * 32;
      float acc = 0.f;
      for (int j = 0; j < 100; j++) acc += att[w * 100 + j] * Hs[j * 64 + k];
      acc *= inv;
      g_xcat[i * 512 + hd * 64 + k] = eluf(acc);
    }
    __syncwarp();
  }
}

// ---------------- Kernel G: output GAT + softmax + loss ----------------------
__global__ __launch_bounds__(128) void final_k(
    const float* __restrict__ outW, const float* __restrict__ outa,
    const float* __restrict__ adj, const int* __restrict__ label,
    float* __restrict__ dout) {
  __shared__ float H2[200], f1s[100], f2s[100], lred[128];
  const int tid = threadIdx.x;
  for (int idx = tid; idx < 200; idx += 128) {
    int i = idx >> 1, c = idx & 1;
    const float* x = g_xcat + i * 512;
    float acc = 0.f;
    for (int k = 0; k < 512; k++) acc += x[k] * outW[k * 2 + c];
    H2[idx] = acc;
  }
  __syncthreads();
  if (tid < 100) {
    f1s[tid] = H2[tid * 2] * outa[0] + H2[tid * 2 + 1] * outa[1];
    f2s[tid] = H2[tid * 2] * outa[2] + H2[tid * 2 + 1] * outa[3];
  }
  __syncthreads();
  float myloss = 0.f;
  if (tid < 100) {
    const int i = tid;
    float fi = f1s[i];
    float m = -INFINITY;
    for (int j = 0; j < 100; j++) {
      if (adj[i * 100 + j] > 0.f) {
        float e = fi + f2s[j];
        e = e > 0.f ? e : 0.2f * e;
        m = fmaxf(m, e);
      }
    }
    float su = 0.f, n0 = 0.f, n1 = 0.f;
    for (int j = 0; j < 100; j++) {
      float wv = 0.f;
      if (adj[i * 100 + j] > 0.f) {
        float e = fi + f2s[j];
        e = e > 0.f ? e : 0.2f * e;
        wv = expf(e - m);
      }
      su += wv;
      n0 += wv * H2[j * 2];
      n1 += wv * H2[j * 2 + 1];
    }
    float x0 = eluf(n0 / su), x1 = eluf(n1 / su);
    float v0 = x0 + g_out1[i * 2], v1 = x1 + g_out1[i * 2 + 1];
    float mm = fmaxf(v0, v1);
    float e0 = expf(v0 - mm), e1 = expf(v1 - mm);
    float o0 = e0 / (e0 + e1), o1 = e1 / (e0 + e1);
    dout[1 + i * 2 + 0] = o0;
    dout[1 + i * 2 + 1] = o1;
    float mo = fmaxf(o0, o1);
    float lse = mo + logf(expf(o0 - mo) + expf(o1 - mo));
    float ol = (label[i] == 0) ? o0 : o1;
    myloss = -(ol - lse);
  }
  lred[tid] = myloss;
  __syncthreads();
  for (int o = 64; o; o >>= 1) {
    if (tid < o) lred[tid] += lred[tid + o];
    __syncthreads();
  }
  if (tid == 0) dout[0] = lred[0] / 100.f;
}

// ---------------- launch -----------------------------------------------------
extern "C" void kernel_launch(void* const* d_in, const int* in_sizes, int n_in,
                              void* d_out, int out_size) {
  const float* text   = (const float*)d_in[0];
  const float* price  = (const float*)d_in[1];
  const int*   label  = (const int*)d_in[2];
  const float* adj    = (const float*)d_in[3];
  const float* pg_Wih = (const float*)d_in[5];
  const float* pg_Whh = (const float*)d_in[6];
  const float* pg_bih = (const float*)d_in[7];
  const float* pg_bhh = (const float*)d_in[8];
  const float* pa_W   = (const float*)d_in[9];
  const float* tg_Wih = (const float*)d_in[10];
  const float* tg_Whh = (const float*)d_in[11];
  const float* tg_bih = (const float*)d_in[12];
  const float* tg_bhh = (const float*)d_in[13];
  const float* ta_W   = (const float*)d_in[14];
  const float* sg_Wih = (const float*)d_in[15];
  const float* sg_Whh = (const float*)d_in[16];
  const float* sg_bih = (const float*)d_in[17];
  const float* sg_bhh = (const float*)d_in[18];
  const float* sa_W   = (const float*)d_in[19];
  const float* bil_B  = (const float*)d_in[20];
  const float* bil_b  = (const float*)d_in[21];
  const float* bl_W   = (const float*)d_in[22];
  const float* bl_b   = (const float*)d_in[23];
  const float* gat_W  = (const float*)d_in[24];
  const float* gat_a  = (const float*)d_in[25];
  const float* out_W  = (const float*)d_in[26];
  const float* out_a  = (const float*)d_in[27];

  cudaFuncSetAttribute(text_rnn,  cudaFuncAttributeMaxDynamicSharedMemorySize, TEXT_RNN_SMEM);
  cudaFuncSetAttribute(price_rnn, cudaFuncAttributeMaxDynamicSharedMemorySize, PRICE_SMEM);
  cudaFuncSetAttribute(seq_rnn,   cudaFuncAttributeMaxDynamicSharedMemorySize, SEQ_SMEM);
  cudaFuncSetAttribute(gat_heads_k, cudaFuncAttributeMaxDynamicSharedMemorySize, GAT_SMEM);

  dim3 gA(10, 3, NS);
  text_gemm<<<gA, dim3(16, 16)>>>(text, tg_Wih, tg_bih);
  text_rnn<<<NS * ND, 192, TEXT_RNN_SMEM>>>(tg_Whh, tg_bhh, ta_W);
  price_rnn<<<NS, 192, PRICE_SMEM>>>(price, pg_Wih, pg_Whh, pg_bih, pg_bhh, pa_W);
  seq_rnn<<<NS, 192, SEQ_SMEM>>>(sg_Wih, sg_Whh, sg_bih, sg_bhh, sa_W);
  bilinear_k<<<NS, 256>>>(bil_B, bil_b, bl_W, bl_b);
  gat_heads_k<<<NHEADS, 256, GAT_SMEM>>>(gat_W, gat_a, adj);
  final_k<<<1, 128>>>(out_W, out_a, adj, label, (float*)d_out);
}

// round 6
// speedup vs baseline: 1.4561x; 1.4561x over previous
#include <cuda_runtime.h>
#include <math.h>
#include <stdint.h>

#define NS 100
#define ND 20
#define NT 30
#define NH_ 64
#define NHEADS 8
#define FTXT 512
#define G3 192   // 3*H

// ---------------- scratch (device globals; no allocs allowed) ----------------
__device__ float g_gi_text[(size_t)NS * ND * NT * G3];   // [s][d*30+t][192]  ~46MB
__device__ float g_news[NS * ND * NH_];                  // [s][d][64]
__device__ float g_price_vec[NS * NH_];
__device__ float g_text_vec[NS * NH_];
__device__ float g_feature[NS * NH_];
__device__ float g_xcat[NS * NHEADS * NH_];              // [i][head*64+k]

__device__ __forceinline__ float sigf(float x) { return 1.f / (1.f + expf(-x)); }
__device__ __forceinline__ float eluf(float x) { return x > 0.f ? x : expm1f(x); }

__device__ __forceinline__ void f2tf(float x, uint32_t& hi, uint32_t& lo) {
  uint32_t h; asm("cvt.rna.tf32.f32 %0, %1;" : "=r"(h) : "f"(x));
  float l = x - __uint_as_float(h);
  uint32_t lb; asm("cvt.rna.tf32.f32 %0, %1;" : "=r"(lb) : "f"(l));
  hi = h; lo = lb;
}

#define MMA_TF32(d, a, b) \
  asm volatile("mma.sync.aligned.m16n8k8.row.col.f32.tf32.tf32.f32 " \
    "{%0,%1,%2,%3}, {%4,%5,%6,%7}, {%8,%9}, {%0,%1,%2,%3};" \
    : "+f"((d)[0]), "+f"((d)[1]), "+f"((d)[2]), "+f"((d)[3]) \
    : "r"((a)[0]), "r"((a)[1]), "r"((a)[2]), "r"((a)[3]), "r"((b)[0]), "r"((b)[1]))

// ---------------- Kernel A: per-stock GEMM (3xTF32 tensor core) --------------
// C[600,192] = X[600,512] @ W[192,512]^T + bih   per stock
#define SA 36  // smem k-stride (32 + 4 pad): bank index (4r+c) all-distinct
__global__ __launch_bounds__(256) void text_gemm(
    const float* __restrict__ X, const float* __restrict__ W,
    const float* __restrict__ bih) {
  const int s  = blockIdx.z;
  const int m0 = blockIdx.x * 64;
  const int n0 = blockIdx.y * 64;
  const float* Xs = X + (size_t)s * 600 * 512;
  const float* Ws = W + (size_t)s * 192 * 512;

  __shared__ uint32_t Ah[64 * SA], Al[64 * SA], Bh[64 * SA], Bl[64 * SA];

  const int tid = threadIdx.x;
  const int lane = tid & 31, wid = tid >> 5;
  const int wm = wid & 1, wn = wid >> 1;       // warp 32x16 tile
  const int gid = lane >> 2, tig = lane & 3;
  const int lrow = tid >> 3;                    // 0..31
  const int lk   = (tid & 7) << 2;              // 0..28

  float acc[2][2][4] = {};

  for (int kt = 0; kt < 16; kt++) {
#pragma unroll
    for (int half = 0; half < 2; half++) {
      int r = lrow + half * 32;
      int gm = m0 + r;
      float4 xv = make_float4(0.f, 0.f, 0.f, 0.f);
      if (gm < 600) xv = *(const float4*)(Xs + (size_t)gm * 512 + kt * 32 + lk);
      uint32_t h0, l0, h1, l1, h2, l2, h3, l3;
      f2tf(xv.x, h0, l0); f2tf(xv.y, h1, l1); f2tf(xv.z, h2, l2); f2tf(xv.w, h3, l3);
      int sa = r * SA + lk;
      *(uint4*)&Ah[sa] = make_uint4(h0, h1, h2, h3);
      *(uint4*)&Al[sa] = make_uint4(l0, l1, l2, l3);
      float4 wv = *(const float4*)(Ws + (size_t)(n0 + r) * 512 + kt * 32 + lk);
      f2tf(wv.x, h0, l0); f2tf(wv.y, h1, l1); f2tf(wv.z, h2, l2); f2tf(wv.w, h3, l3);
      *(uint4*)&Bh[sa] = make_uint4(h0, h1, h2, h3);
      *(uint4*)&Bl[sa] = make_uint4(l0, l1, l2, l3);
    }
    __syncthreads();
#pragma unroll
    for (int ks = 0; ks < 4; ks++) {
      const int k0 = ks * 8;
      uint32_t ah[2][4], al[2][4], bh[2][2], bl[2][2];
#pragma unroll
      for (int mt = 0; mt < 2; mt++) {
        int rb = (wm * 32 + mt * 16 + gid) * SA + k0 + tig;
        ah[mt][0] = Ah[rb];           ah[mt][1] = Ah[rb + 8 * SA];
        ah[mt][2] = Ah[rb + 4];       ah[mt][3] = Ah[rb + 8 * SA + 4];
        al[mt][0] = Al[rb];           al[mt][1] = Al[rb + 8 * SA];
        al[mt][2] = Al[rb + 4];       al[mt][3] = Al[rb + 8 * SA + 4];
      }
#pragma unroll
      for (int nt = 0; nt < 2; nt++) {
        int cb = (wn * 16 + nt * 8 + gid) * SA + k0 + tig;
        bh[nt][0] = Bh[cb]; bh[nt][1] = Bh[cb + 4];
        bl[nt][0] = Bl[cb]; bl[nt][1] = Bl[cb + 4];
      }
#pragma unroll
      for (int mt = 0; mt < 2; mt++)
#pragma unroll
        for (int nt = 0; nt < 2; nt++) {
          MMA_TF32(acc[mt][nt], ah[mt], bh[nt]);
          MMA_TF32(acc[mt][nt], al[mt], bh[nt]);
          MMA_TF32(acc[mt][nt], ah[mt], bl[nt]);
        }
    }
    __syncthreads();
  }
  float* Cs = g_gi_text + (size_t)s * 600 * 192;
#pragma unroll
  for (int mt = 0; mt < 2; mt++)
#pragma unroll
    for (int nt = 0; nt < 2; nt++) {
      int row = m0 + wm * 32 + mt * 16 + gid;
      int col = n0 + wn * 16 + nt * 8 + tig * 2;
      float b0 = bih[s * 192 + col], b1 = bih[s * 192 + col + 1];
      if (row < 600) {
        Cs[(size_t)row * 192 + col]     = acc[mt][nt][0] + b0;
        Cs[(size_t)row * 192 + col + 1] = acc[mt][nt][1] + b1;
      }
      if (row + 8 < 600) {
        Cs[(size_t)(row + 8) * 192 + col]     = acc[mt][nt][2] + b0;
        Cs[(size_t)(row + 8) * 192 + col + 1] = acc[mt][nt][3] + b1;
      }
    }
}

// ---------------- Kernel B: text GRU, 4 days per block + attention -----------
// smem: WhhT[64*192] outs[4*30*64] h[4*64] gh[4*192] sc[4*32] at[4*32]
#define TEXT_RNN_SMEM ((64 * 192 + 4 * 30 * 64 + 4 * 64 + 4 * 192 + 128 + 128) * 4)
__global__ __launch_bounds__(256) void text_rnn(
    const float* __restrict__ Whh, const float* __restrict__ bhh,
    const float* __restrict__ Wa) {
  const int b = blockIdx.x;
  const int s = b / 5, d0 = (b % 5) * 4;
  extern __shared__ float sm[];
  float* WhhT = sm;                    // [k][g]
  float* outs = WhhT + 64 * 192;       // [d][t][h]
  float* hsh  = outs + 4 * 30 * 64;    // [d][h]
  float* gh   = hsh + 4 * 64;          // [d][g]
  float* sc   = gh + 4 * 192;          // [d][32]
  float* at   = sc + 128;              // [d][32]
  const int tid = threadIdx.x;
  const int lane = tid & 31, wid = tid >> 5;

  const float* Whs = Whh + (size_t)s * 192 * 64;
  for (int idx = tid; idx < 192 * 64; idx += 256) {
    int g = idx >> 6, k = idx & 63;
    WhhT[k * 192 + g] = Whs[idx];
  }
  if (tid < 256) hsh[tid] = 0.f;
  float bh = (tid < 192) ? bhh[s * 192 + tid] : 0.f;
  const float* gib = g_gi_text + ((size_t)s * 600 + d0 * 30) * 192;
  __syncthreads();

  for (int t = 0; t < 30; t++) {
    if (tid < 192) {
      const int g = tid;
      float a0 = bh, a1 = bh, a2 = bh, a3 = bh;
#pragma unroll
      for (int k = 0; k < 64; k++) {
        float w = WhhT[k * 192 + g];
        a0 += w * hsh[k];       a1 += w * hsh[64 + k];
        a2 += w * hsh[128 + k]; a3 += w * hsh[192 + k];
      }
      gh[g] = a0; gh[192 + g] = a1; gh[384 + g] = a2; gh[576 + g] = a3;
    }
    __syncthreads();
    {
      const int d = tid >> 6, h = tid & 63;
      const float* gi = gib + ((size_t)d * 30 + t) * 192;
      const float* gd = gh + d * 192;
      float r = sigf(gi[h] + gd[h]);
      float z = sigf(gi[64 + h] + gd[64 + h]);
      float n = tanhf(gi[128 + h] + r * gd[128 + h]);
      float hn = (1.f - z) * n + z * hsh[d * 64 + h];
      hsh[d * 64 + h] = hn;
      outs[(d * 30 + t) * 64 + h] = hn;
    }
    __syncthreads();
  }

  // attention pool per day
  const float* Was = Wa + (size_t)s * 64 * 64;
  {
    const int d = wid >> 1, half = wid & 1;
    for (int t = half; t < 30; t += 2) {
      const float* ot = outs + (d * 30 + t) * 64;
      float sacc = 0.f;
#pragma unroll
      for (int kh = 0; kh < 2; kh++) {
        int k = lane + kh * 32;
        float p = 0.f;
#pragma unroll
        for (int j = 0; j < 64; j++) p += ot[j] * Was[j * 64 + k];
        sacc += tanhf(p) * hsh[d * 64 + k];
      }
      for (int o = 16; o; o >>= 1) sacc += __shfl_xor_sync(0xffffffffu, sacc, o);
      if (lane == 0) sc[d * 32 + t] = sacc;
    }
  }
  __syncthreads();
  if (wid < 4) {
    const int d = wid;
    float v = (lane < 30) ? sc[d * 32 + lane] : -INFINITY;
    float m = v;
    for (int o = 16; o; o >>= 1) m = fmaxf(m, __shfl_xor_sync(0xffffffffu, m, o));
    float e = (lane < 30) ? expf(v - m) : 0.f;
    float su = e;
    for (int o = 16; o; o >>= 1) su += __shfl_xor_sync(0xffffffffu, su, o);
    if (lane < 30) at[d * 32 + lane] = e / su;
  }
  __syncthreads();
  {
    const int d = tid >> 6, h = tid & 63;
    float acc = 0.f;
    for (int t = 0; t < 30; t++) acc += at[d * 32 + t] * outs[(d * 30 + t) * 64 + h];
    g_news[(s * ND + d0 + d) * 64 + h] = acc;
  }
}

// ---------------- Kernel C: price GRU (gi hoisted) + attention ---------------
#define PRICE_SMEM ((64 * 192 + 20 * 64 + 20 * 192 + 64 + 192 + 32 + 32) * 4)
__global__ __launch_bounds__(192) void price_rnn(
    const float* __restrict__ price, const float* __restrict__ Wih,
    const float* __restrict__ Whh, const float* __restrict__ bih,
    const float* __restrict__ bhh, const float* __restrict__ Wa) {
  const int s = blockIdx.x;
  extern __shared__ float sm[];
  float* WhhT = sm;
  float* outs = WhhT + 64 * 192;   // [20][64]
  float* gis  = outs + 20 * 64;    // [20][192]
  float* hbuf = gis + 20 * 192;
  float* gh   = hbuf + 64;
  float* sc   = gh + 192;
  float* at   = sc + 32;
  const int tid = threadIdx.x;

  const float* Whs = Whh + (size_t)s * 192 * 64;
  for (int idx = tid; idx < 192 * 64; idx += 192) {
    int g = idx >> 6, k = idx & 63;
    WhhT[k * 192 + g] = Whs[idx];
  }
  if (tid < 64) hbuf[tid] = 0.f;
  const float bh = bhh[s * 192 + tid];
  {
    const float bi = bih[s * 192 + tid];
    const float wi0 = Wih[(s * 192 + tid) * 3 + 0];
    const float wi1 = Wih[(s * 192 + tid) * 3 + 1];
    const float wi2 = Wih[(s * 192 + tid) * 3 + 2];
    for (int t = 0; t < 20; t++) {
      const float* x = price + ((size_t)s * 20 + t) * 3;
      gis[t * 192 + tid] = bi + wi0 * x[0] + wi1 * x[1] + wi2 * x[2];
    }
  }
  __syncthreads();

  for (int t = 0; t < 20; t++) {
    float acc = bh;
#pragma unroll
    for (int k = 0; k < 64; k++) acc += WhhT[k * 192 + tid] * hbuf[k];
    gh[tid] = acc;
    __syncthreads();
    if (tid < 64) {
      const float* gi = gis + t * 192;
      float r = sigf(gi[tid] + gh[tid]);
      float z = sigf(gi[64 + tid] + gh[64 + tid]);
      float n = tanhf(gi[128 + tid] + r * gh[128 + tid]);
      float hn = (1.f - z) * n + z * hbuf[tid];
      hbuf[tid] = hn;
      outs[t * 64 + tid] = hn;
    }
    __syncthreads();
  }

  const float* Was = Wa + (size_t)s * 64 * 64;
  const int w = tid >> 5, lane = tid & 31;
  for (int t = w; t < 20; t += 6) {
    float sacc = 0.f;
#pragma unroll
    for (int kh = 0; kh < 2; kh++) {
      int k = lane + kh * 32;
      float p = 0.f;
#pragma unroll
      for (int j = 0; j < 64; j++) p += outs[t * 64 + j] * Was[j * 64 + k];
      sacc += tanhf(p) * hbuf[k];
    }
    for (int o = 16; o; o >>= 1) sacc += __shfl_xor_sync(0xffffffffu, sacc, o);
    if (lane == 0) sc[t] = sacc;
  }
  __syncthreads();
  if (tid < 32) {
    float v = (tid < 20) ? sc[tid] : -INFINITY;
    float m = v;
    for (int o = 16; o; o >>= 1) m = fmaxf(m, __shfl_xor_sync(0xffffffffu, m, o));
    float e = (tid < 20) ? expf(v - m) : 0.f;
    float su = e;
    for (int o = 16; o; o >>= 1) su += __shfl_xor_sync(0xffffffffu, su, o);
    if (tid < 20) at[tid] = e / su;
  }
  __syncthreads();
  if (tid < 64) {
    float acc = 0.f;
    for (int t = 0; t < 20; t++) acc += at[t] * outs[t * 64 + tid];
    g_price_vec[s * 64 + tid] = acc;
  }
}

// ---------------- Kernel D: day-sequence GRU (gi hoisted) + attention --------
#define SEQ_SMEM ((64 * 192 * 2 + 20 * 64 * 2 + 20 * 192 + 64 + 192 + 32 + 32) * 4)
__global__ __launch_bounds__(192) void seq_rnn(
    const float* __restrict__ Wih, const float* __restrict__ Whh,
    const float* __restrict__ bih, const float* __restrict__ bhh,
    const float* __restrict__ Wa) {
  const int s = blockIdx.x;
  extern __shared__ float sm[];
  float* WihT = sm;                   // [k][g]
  float* WhhT = WihT + 64 * 192;
  float* ns   = WhhT + 64 * 192;      // [20][64]
  float* outs = ns + 20 * 64;         // [20][64]
  float* gis  = outs + 20 * 64;       // [20][192]
  float* hbuf = gis + 20 * 192;
  float* gh   = hbuf + 64;
  float* sc   = gh + 192;
  float* at   = sc + 32;
  const int tid = threadIdx.x;

  const float* Wis = Wih + (size_t)s * 192 * 64;
  const float* Whs = Whh + (size_t)s * 192 * 64;
  for (int idx = tid; idx < 192 * 64; idx += 192) {
    int g = idx >> 6, k = idx & 63;
    WihT[k * 192 + g] = Wis[idx];
    WhhT[k * 192 + g] = Whs[idx];
  }
  for (int idx = tid; idx < 20 * 64; idx += 192) ns[idx] = g_news[s * 20 * 64 + idx];
  if (tid < 64) hbuf[tid] = 0.f;
  const float bh = bhh[s * 192 + tid];
  const float bi = bih[s * 192 + tid];
  __syncthreads();

  // hoisted input projections: gis[t][g] = bi + sum_k WihT[k][g]*ns[t][k]
  {
    float acc[20];
#pragma unroll
    for (int t = 0; t < 20; t++) acc[t] = bi;
#pragma unroll 8
    for (int k = 0; k < 64; k++) {
      float w = WihT[k * 192 + tid];
#pragma unroll
      for (int t = 0; t < 20; t++) acc[t] += w * ns[t * 64 + k];
    }
#pragma unroll
    for (int t = 0; t < 20; t++) gis[t * 192 + tid] = acc[t];
  }
  __syncthreads();

  for (int t = 0; t < 20; t++) {
    float acc = bh;
#pragma unroll
    for (int k = 0; k < 64; k++) acc += WhhT[k * 192 + tid] * hbuf[k];
    gh[tid] = acc;
    __syncthreads();
    if (tid < 64) {
      const float* gi = gis + t * 192;
      float r = sigf(gi[tid] + gh[tid]);
      float z = sigf(gi[64 + tid] + gh[64 + tid]);
      float n = tanhf(gi[128 + tid] + r * gh[128 + tid]);
      float hn = (1.f - z) * n + z * hbuf[tid];
      hbuf[tid] = hn;
      outs[t * 64 + tid] = hn;
    }
    __syncthreads();
  }

  const float* Was = Wa + (size_t)s * 64 * 64;
  const int w = tid >> 5, lane = tid & 31;
  for (int t = w; t < 20; t += 6) {
    float sacc = 0.f;
#pragma unroll
    for (int kh = 0; kh < 2; kh++) {
      int k = lane + kh * 32;
      float p = 0.f;
#pragma unroll
      for (int j = 0; j < 64; j++) p += outs[t * 64 + j] * Was[j * 64 + k];
      sacc += tanhf(p) * hbuf[k];
    }
    for (int o = 16; o; o >>= 1) sacc += __shfl_xor_sync(0xffffffffu, sacc, o);
    if (lane == 0) sc[t] = sacc;
  }
  __syncthreads();
  if (tid < 32) {
    float v = (tid < 20) ? sc[tid] : -INFINITY;
    float m = v;
    for (int o = 16; o; o >>= 1) m = fmaxf(m, __shfl_xor_sync(0xffffffffu, m, o));
    float e = (tid < 20) ? expf(v - m) : 0.f;
    float su = e;
    for (int o = 16; o; o >>= 1) su += __shfl_xor_sync(0xffffffffu, su, o);
    if (tid < 20) at[tid] = e / su;
  }
  __syncthreads();
  if (tid < 64) {
    float acc = 0.f;
    for (int t = 0; t < 20; t++) acc += at[t] * outs[t * 64 + tid];
    g_text_vec[s * 64 + tid] = acc;
  }
}

// ---------------- Kernel E: bilinear fusion (split over 8 y-blocks) ----------
__global__ __launch_bounds__(256) void bilinear_k(
    const float* __restrict__ B, const float* __restrict__ bb) {
  const int s = blockIdx.x;
  __shared__ float tv[64], pv[64];
  const int tid = threadIdx.x;
  if (tid < 64) { tv[tid] = g_text_vec[s * 64 + tid]; pv[tid] = g_price_vec[s * 64 + tid]; }
  __syncthreads();
  const int w = tid >> 5, lane = tid & 31;
  const int o = blockIdx.y * 8 + w;
  const float* Bo = B + ((size_t)s * 64 + o) * 4096;
  float acc = 0.f;
  for (int i = 0; i < 32; i++) {
    int base = i * 128 + lane * 4;
    float4 b4 = *(const float4*)(Bo + base);
    float ti = tv[base >> 6];
    int pj = base & 63;
    acc += ti * (b4.x * pv[pj] + b4.y * pv[pj + 1] + b4.z * pv[pj + 2] + b4.w * pv[pj + 3]);
  }
  for (int of = 16; of; of >>= 1) acc += __shfl_xor_sync(0xffffffffu, acc, of);
  if (lane == 0) g_feature[s * 64 + o] = tanhf(acc + bb[s * 64 + o]);
}

// ---------------- Kernel F: 8 GAT heads --------------------------------------
#define GAT_SMEM ((6400 + 6400 + 4096 + 128 + 128 + 128 + 800) * 4)
__global__ __launch_bounds__(256) void gat_heads_k(
    const float* __restrict__ gatW, const float* __restrict__ gata,
    const float* __restrict__ adj) {
  const int hd = blockIdx.x;
  extern __shared__ float sm[];
  float* Fs = sm;            // [100][64]
  float* Hs = Fs + 6400;     // [100][64]
  float* Ws = Hs + 6400;     // [64][64]
  float* av = Ws + 4096;     // [128]
  float* f1 = av + 128;      // [100]
  float* f2 = f1 + 128;      // [100]
  float* att = f2 + 128;     // [8][100]
  const int tid = threadIdx.x;

  for (int idx = tid; idx < 6400; idx += 256) Fs[idx] = g_feature[idx];
  for (int idx = tid; idx < 4096; idx += 256) Ws[idx] = gatW[hd * 4096 + idx];
  if (tid < 128) av[tid] = gata[hd * 128 + tid];
  __syncthreads();
  for (int idx = tid; idx < 6400; idx += 256) {
    int i = idx >> 6, k = idx & 63;
    float acc = 0.f;
#pragma unroll
    for (int j = 0; j < 64; j++) acc += Fs[i * 64 + j] * Ws[j * 64 + k];
    Hs[idx] = acc;
  }
  __syncthreads();
  if (tid < 100) {
    float a1 = 0.f, a2 = 0.f;
    for (int k = 0; k < 64; k++) {
      float h = Hs[tid * 64 + k];
      a1 += h * av[k]; a2 += h * av[64 + k];
    }
    f1[tid] = a1; f2[tid] = a2;
  }
  __syncthreads();
  const int w = tid >> 5, lane = tid & 31;
  for (int i = w; i < 100; i += 8) {
    float fi = f1[i];
    float ev[4];
    float m = -INFINITY;
#pragma unroll
    for (int q = 0; q < 4; q++) {
      int j = lane + q * 32;
      float e = -INFINITY;
      if (j < 100 && adj[i * 100 + j] > 0.f) {
        e = fi + f2[j];
        e = e > 0.f ? e : 0.2f * e;
      }
      ev[q] = e;
      m = fmaxf(m, e);
    }
    for (int o = 16; o; o >>= 1) m = fmaxf(m, __shfl_xor_sync(0xffffffffu, m, o));
    float su = 0.f;
#pragma unroll
    for (int q = 0; q < 4; q++) {
      int j = lane + q * 32;
      float wv = (ev[q] == -INFINITY) ? 0.f : expf(ev[q] - m);
      if (j < 100) att[w * 100 + j] = wv;
      su += wv;
    }
    for (int o = 16; o; o >>= 1) su += __shfl_xor_sync(0xffffffffu, su, o);
    float inv = 1.f / su;
    __syncwarp();
#pragma unroll
    for (int kh = 0; kh < 2; kh++) {
      int k = lane + kh * 32;
      float acc = 0.f;
      for (int j = 0; j < 100; j++) acc += att[w * 100 + j] * Hs[j * 64 + k];
      acc *= inv;
      g_xcat[i * 512 + hd * 64 + k] = eluf(acc);
    }
    __syncwarp();
  }
}

// ---------------- Kernel G: blend + output GAT + softmax + loss --------------
__global__ __launch_bounds__(128) void final_k(
    const float* __restrict__ outW, const float* __restrict__ outa,
    const float* __restrict__ adj, const int* __restrict__ label,
    const float* __restrict__ blW, const float* __restrict__ blb,
    float* __restrict__ dout) {
  __shared__ float H2[200], f1s[100], f2s[100], out1s[200], lred[128];
  const int tid = threadIdx.x;
  for (int idx = tid; idx < 200; idx += 128) {
    int i = idx >> 1, c = idx & 1;
    const float* x = g_xcat + i * 512;
    float acc = 0.f;
    for (int k = 0; k < 512; k++) acc += x[k] * outW[k * 2 + c];
    H2[idx] = acc;
    const float* f = g_feature + i * 64;
    float a = blb[c];
    for (int k = 0; k < 64; k++) a += f[k] * blW[k * 2 + c];
    out1s[idx] = tanhf(a);
  }
  __syncthreads();
  if (tid < 100) {
    f1s[tid] = H2[tid * 2] * outa[0] + H2[tid * 2 + 1] * outa[1];
    f2s[tid] = H2[tid * 2] * outa[2] + H2[tid * 2 + 1] * outa[3];
  }
  __syncthreads();
  float myloss = 0.f;
  if (tid < 100) {
    const int i = tid;
    float fi = f1s[i];
    float m = -INFINITY;
    for (int j = 0; j < 100; j++) {
      if (adj[i * 100 + j] > 0.f) {
        float e = fi + f2s[j];
        e = e > 0.f ? e : 0.2f * e;
        m = fmaxf(m, e);
      }
    }
    float su = 0.f, n0 = 0.f, n1 = 0.f;
    for (int j = 0; j < 100; j++) {
      float wv = 0.f;
      if (adj[i * 100 + j] > 0.f) {
        float e = fi + f2s[j];
        e = e > 0.f ? e : 0.2f * e;
        wv = expf(e - m);
      }
      su += wv;
      n0 += wv * H2[j * 2];
      n1 += wv * H2[j * 2 + 1];
    }
    float x0 = eluf(n0 / su), x1 = eluf(n1 / su);
    float v0 = x0 + out1s[i * 2], v1 = x1 + out1s[i * 2 + 1];
    float mm = fmaxf(v0, v1);
    float e0 = expf(v0 - mm), e1 = expf(v1 - mm);
    float o0 = e0 / (e0 + e1), o1 = e1 / (e0 + e1);
    dout[1 + i * 2 + 0] = o0;
    dout[1 + i * 2 + 1] = o1;
    float mo = fmaxf(o0, o1);
    float lse = mo + logf(expf(o0 - mo) + expf(o1 - mo));
    float ol = (label[i] == 0) ? o0 : o1;
    myloss = -(ol - lse);
  }
  lred[tid] = myloss;
  __syncthreads();
  for (int o = 64; o; o >>= 1) {
    if (tid < o) lred[tid] += lred[tid + o];
    __syncthreads();
  }
  if (tid == 0) dout[0] = lred[0] / 100.f;
}

// ---------------- launch -----------------------------------------------------
extern "C" void kernel_launch(void* const* d_in, const int* in_sizes, int n_in,
                              void* d_out, int out_size) {
  const float* text   = (const float*)d_in[0];
  const float* price  = (const float*)d_in[1];
  const int*   label  = (const int*)d_in[2];
  const float* adj    = (const float*)d_in[3];
  const float* pg_Wih = (const float*)d_in[5];
  const float* pg_Whh = (const float*)d_in[6];
  const float* pg_bih = (const float*)d_in[7];
  const float* pg_bhh = (const float*)d_in[8];
  const float* pa_W   = (const float*)d_in[9];
  const float* tg_Wih = (const float*)d_in[10];
  const float* tg_Whh = (const float*)d_in[11];
  const float* tg_bih = (const float*)d_in[12];
  const float* tg_bhh = (const float*)d_in[13];
  const float* ta_W   = (const float*)d_in[14];
  const float* sg_Wih = (const float*)d_in[15];
  const float* sg_Whh = (const float*)d_in[16];
  const float* sg_bih = (const float*)d_in[17];
  const float* sg_bhh = (const float*)d_in[18];
  const float* sa_W   = (const float*)d_in[19];
  const float* bil_B  = (const float*)d_in[20];
  const float* bil_b  = (const float*)d_in[21];
  const float* bl_W   = (const float*)d_in[22];
  const float* bl_b   = (const float*)d_in[23];
  const float* gat_W  = (const float*)d_in[24];
  const float* gat_a  = (const float*)d_in[25];
  const float* out_W  = (const float*)d_in[26];
  const float* out_a  = (const float*)d_in[27];

  cudaFuncSetAttribute(text_rnn,  cudaFuncAttributeMaxDynamicSharedMemorySize, TEXT_RNN_SMEM);
  cudaFuncSetAttribute(price_rnn, cudaFuncAttributeMaxDynamicSharedMemorySize, PRICE_SMEM);
  cudaFuncSetAttribute(seq_rnn,   cudaFuncAttributeMaxDynamicSharedMemorySize, SEQ_SMEM);
  cudaFuncSetAttribute(gat_heads_k, cudaFuncAttributeMaxDynamicSharedMemorySize, GAT_SMEM);

  dim3 gA(10, 3, NS);
  text_gemm<<<gA, 256>>>(text, tg_Wih, tg_bih);
  text_rnn<<<NS * 5, 256, TEXT_RNN_SMEM>>>(tg_Whh, tg_bhh, ta_W);
  price_rnn<<<NS, 192, PRICE_SMEM>>>(price, pg_Wih, pg_Whh, pg_bih, pg_bhh, pa_W);
  seq_rnn<<<NS, 192, SEQ_SMEM>>>(sg_Wih, sg_Whh, sg_bih, sg_bhh, sa_W);
  bilinear_k<<<dim3(NS, 8), 256>>>(bil_B, bil_b);
  gat_heads_k<<<NHEADS, 256, GAT_SMEM>>>(gat_W, gat_a, adj);
  final_k<<<1, 128>>>(out_W, out_a, adj, label, bl_W, bl_b, (float*)d_out);
}